// round 3
// baseline (speedup 1.0000x reference)
#include <cuda_runtime.h>

#define NN 4096
#define DD 256
#define HH 4
#define HD 64
#define TD 768           // 3*D
#define WPR 128          // bitmap words per row (4096/32)
#define MAXN 640         // max neighbors per row (deg ~ Poisson(65); overflow prob ~0)

// ---------------- scratch (__device__ globals; no allocation allowed) -------
__device__ unsigned int g_bitmap[NN * WPR];            // 2 MB adjacency bitmap
__device__ __align__(16) float g_qkv[NN * TD];         // 12 MB packed QKV (q pre-scaled)
__device__ float g_ctx[NN * DD];                       // 4 MB attention context
__device__ float g_att[NN * DD];                       // 4 MB after out_proj
__device__ float g_fin[NN * DD];                       // 4 MB pre-LN (proj + residual)

// source/dest selectors for the GEMM template (device-symbol access only)
#define SRC_EXT 0
#define SRC_CTX 1
#define SRC_ATT 2
#define DST_QKV 0
#define DST_ATT 1
#define DST_FIN 2

// ---------------- bitmap init: zero + diagonal (self loops) -----------------
__global__ void k_init_bitmap() {
    int w = blockIdx.x * 256 + threadIdx.x;          // 0 .. NN*WPR-1
    int row = w >> 7;
    int cw  = w & 127;
    g_bitmap[w] = ((row >> 5) == cw) ? (1u << (row & 31)) : 0u;
}

// ---------------- scatter edges (symmetrized); edge_index is INT32 ----------
__global__ void k_edges(const int* __restrict__ ei, int E) {
    int e = blockIdx.x * 256 + threadIdx.x;
    if (e >= E) return;
    int s = ei[e];
    int d = ei[E + e];
    atomicOr(&g_bitmap[s * WPR + (d >> 5)], 1u << (d & 31));
    atomicOr(&g_bitmap[d * WPR + (s >> 5)], 1u << (s & 31));
}

// ---------------- tiled fp32 GEMM: C[M x Nn] = A[M x 256] * B[Nn x 256]^T ---
template <int SRC, int DST, bool QSCALE, bool RESID>
__global__ void k_gemm(const float* __restrict__ Aext,
                       const float* __restrict__ B,
                       const float* __restrict__ bias,
                       const float* __restrict__ resid, int Nn) {
    const float* A = (SRC == SRC_EXT) ? Aext : (SRC == SRC_CTX ? g_ctx : g_att);
    float* C = (DST == DST_QKV) ? g_qkv : (DST == DST_ATT ? g_att : g_fin);

    __shared__ float As[64][33];
    __shared__ float Bs[64][33];
    int t  = threadIdx.x;
    int m0 = blockIdx.y * 64;
    int n0 = blockIdx.x * 64;
    int tm = t >> 4, tn = t & 15;

    float acc[4][4] = {};
    for (int k0 = 0; k0 < 256; k0 += 32) {
        for (int idx = t; idx < 64 * 32; idx += 256) {
            int r = idx >> 5, c = idx & 31;
            As[r][c] = A[(m0 + r) * 256 + k0 + c];
            Bs[r][c] = B[(n0 + r) * 256 + k0 + c];
        }
        __syncthreads();
#pragma unroll
        for (int kk = 0; kk < 32; kk++) {
            float a[4], b[4];
#pragma unroll
            for (int x = 0; x < 4; x++) { a[x] = As[tm * 4 + x][kk]; b[x] = Bs[tn * 4 + x][kk]; }
#pragma unroll
            for (int x = 0; x < 4; x++)
#pragma unroll
                for (int y = 0; y < 4; y++) acc[x][y] += a[x] * b[y];
        }
        __syncthreads();
    }
#pragma unroll
    for (int x = 0; x < 4; x++) {
        int row = m0 + tm * 4 + x;
#pragma unroll
        for (int y = 0; y < 4; y++) {
            int col = n0 + tn * 4 + y;
            float v = acc[x][y] + bias[col];
            if (QSCALE && col < 256) v *= 0.125f;   // 1/sqrt(HD)
            if (RESID) v += resid[row * 256 + col];
            C[row * Nn + col] = v;
        }
    }
}

// ---------------- sparse masked multi-head attention ------------------------
// One block per query node. Deterministic neighbor compaction (popcount+scan).
__global__ void k_attn() {
    int i = blockIdx.x;
    __shared__ float q_s[256];
    __shared__ int   nbr[MAXN];
    __shared__ float sc[MAXN * 4];
    __shared__ float inv_s[4];
    __shared__ int   wsum[4];      // per-warp popcount sums (warps 0-3 hold words)
    __shared__ int   total;

    int t = threadIdx.x;
    int warp = t >> 5, lane = t & 31;
    q_s[t] = g_qkv[i * TD + t];        // pre-scaled Q, 4 heads concatenated

    // --- deterministic neighbor extraction: popcount + exclusive scan -------
    unsigned w = 0; int pc = 0;
    if (t < 128) { w = g_bitmap[i * WPR + t]; pc = __popc(w); }
    // intra-warp exclusive scan (warps 0-3)
    int excl = 0;
    if (t < 128) {
        int v = pc;
#pragma unroll
        for (int o = 1; o < 32; o <<= 1) {
            int u = __shfl_up_sync(0xffffffffu, v, o);
            if (lane >= o) v += u;
        }
        excl = v - pc;                       // exclusive within warp
        if (lane == 31) wsum[warp] = v;      // warp total
    }
    __syncthreads();
    if (t == 0) {
        int s0 = wsum[0], s1 = wsum[1], s2 = wsum[2], s3 = wsum[3];
        wsum[0] = 0; wsum[1] = s0; wsum[2] = s0 + s1; wsum[3] = s0 + s1 + s2;
        total = s0 + s1 + s2 + s3;
    }
    __syncthreads();
    if (t < 128) {
        int base = wsum[warp] + excl;
        unsigned ww = w;
        int j = 0;
        while (ww) {
            int b = __ffs(ww) - 1;
            ww &= ww - 1;
            int p = base + j++;
            if (p < MAXN) nbr[p] = t * 32 + b;
        }
    }
    __syncthreads();
    int c = total < MAXN ? total : MAXN;

    int head = lane >> 3;              // lanes 0-7 -> head0 ... 24-31 -> head3

    // --- scores: warp per neighbor (strided), 8 floats of K per lane --------
    for (int n = warp; n < c; n += 8) {
        const float* kr = g_qkv + nbr[n] * TD + 256 + lane * 8;
        float4 k0 = *(const float4*)kr;
        float4 k1 = *(const float4*)(kr + 4);
        const float* qq = q_s + lane * 8;
        float p = k0.x * qq[0] + k0.y * qq[1] + k0.z * qq[2] + k0.w * qq[3]
                + k1.x * qq[4] + k1.y * qq[5] + k1.z * qq[6] + k1.w * qq[7];
        p += __shfl_xor_sync(0xffffffffu, p, 4);
        p += __shfl_xor_sync(0xffffffffu, p, 2);
        p += __shfl_xor_sync(0xffffffffu, p, 1);
        if ((lane & 7) == 0) sc[n * 4 + head] = p;
    }
    __syncthreads();

    // --- softmax per head (warp h handles head h) ---------------------------
    if (warp < 4) {
        int h = warp;
        float m = -1e30f;
        for (int n = lane; n < c; n += 32) m = fmaxf(m, sc[n * 4 + h]);
#pragma unroll
        for (int o = 16; o; o >>= 1) m = fmaxf(m, __shfl_xor_sync(0xffffffffu, m, o));
        float s = 0.f;
        for (int n = lane; n < c; n += 32) {
            float e = expf(sc[n * 4 + h] - m);
            sc[n * 4 + h] = e;
            s += e;
        }
#pragma unroll
        for (int o = 16; o; o >>= 1) s += __shfl_xor_sync(0xffffffffu, s, o);
        if (lane == 0) inv_s[h] = 1.0f / s;
    }
    __syncthreads();

    // --- context: thread t = output channel t; coalesced V gathers ----------
    int h2 = t >> 6;
    float a0 = 0.f, a1 = 0.f, a2 = 0.f, a3 = 0.f;
    int n = 0;
    for (; n + 4 <= c; n += 4) {
        a0 += sc[(n + 0) * 4 + h2] * g_qkv[nbr[n + 0] * TD + 512 + t];
        a1 += sc[(n + 1) * 4 + h2] * g_qkv[nbr[n + 1] * TD + 512 + t];
        a2 += sc[(n + 2) * 4 + h2] * g_qkv[nbr[n + 2] * TD + 512 + t];
        a3 += sc[(n + 3) * 4 + h2] * g_qkv[nbr[n + 3] * TD + 512 + t];
    }
    for (; n < c; n++)
        a0 += sc[n * 4 + h2] * g_qkv[nbr[n] * TD + 512 + t];
    g_ctx[i * DD + t] = ((a0 + a1) + (a2 + a3)) * inv_s[h2];
}

// ---------------- LayerNorm over last dim (256), one block per row ----------
__global__ void k_ln(const float* __restrict__ gamma,
                     const float* __restrict__ beta,
                     float* __restrict__ out) {
    int i = blockIdx.x, t = threadIdx.x;
    __shared__ float red[8];
    float v = g_fin[i * 256 + t];

    float s = v;
#pragma unroll
    for (int o = 16; o; o >>= 1) s += __shfl_xor_sync(0xffffffffu, s, o);
    if ((t & 31) == 0) red[t >> 5] = s;
    __syncthreads();
    float mu = 0.f;
#pragma unroll
    for (int j = 0; j < 8; j++) mu += red[j];
    mu *= (1.0f / 256.0f);
    __syncthreads();                      // red reused below

    float d = v - mu;
    float s2 = d * d;
#pragma unroll
    for (int o = 16; o; o >>= 1) s2 += __shfl_xor_sync(0xffffffffu, s2, o);
    if ((t & 31) == 0) red[t >> 5] = s2;
    __syncthreads();
    float var = 0.f;
#pragma unroll
    for (int j = 0; j < 8; j++) var += red[j];
    var *= (1.0f / 256.0f);

    out[i * 256 + t] = d * rsqrtf(var + 1e-5f) * gamma[t] + beta[t];
}

// ---------------- launch ----------------------------------------------------
extern "C" void kernel_launch(void* const* d_in, const int* in_sizes, int n_in,
                              void* d_out, int out_size) {
    const float* nf    = (const float*)d_in[0];
    const int*   ei    = (const int*)d_in[1];      // int32! (jax x64 disabled)
    const float* in_w  = (const float*)d_in[2];
    const float* in_b  = (const float*)d_in[3];
    const float* out_w = (const float*)d_in[4];
    const float* out_b = (const float*)d_in[5];
    const float* p_w   = (const float*)d_in[6];
    const float* p_b   = (const float*)d_in[7];
    const float* gamma = (const float*)d_in[8];
    const float* beta  = (const float*)d_in[9];
    int E = in_sizes[1] / 2;

    k_init_bitmap<<<(NN * WPR) / 256, 256>>>();
    k_edges<<<(E + 255) / 256, 256>>>(ei, E);
    k_gemm<SRC_EXT, DST_QKV, true,  false><<<dim3(TD / 64, NN / 64), 256>>>(nf, in_w, in_b, nullptr, TD);
    k_attn<<<NN, 256>>>();
    k_gemm<SRC_CTX, DST_ATT, false, false><<<dim3(DD / 64, NN / 64), 256>>>(nullptr, out_w, out_b, nullptr, DD);
    k_gemm<SRC_ATT, DST_FIN, false, true ><<<dim3(DD / 64, NN / 64), 256>>>(nullptr, p_w, p_b, nf, DD);
    k_ln<<<NN, 256>>>(gamma, beta, (float*)d_out);
}

// round 5
// speedup vs baseline: 1.5521x; 1.5521x over previous
#include <cuda_runtime.h>
#include <cuda_bf16.h>
#include <cstdint>

#define NN 4096
#define DD 256
#define TD 768
#define WPR 128
#define MAXN 640

// ---------------- scratch ----------------------------------------------------
__device__ unsigned int g_bitmap[NN * WPR];
__device__ __align__(16) float g_qkv[NN * TD];
__device__ __align__(16) float g_ctx[NN * DD];
__device__ __align__(16) float g_att[NN * DD];
__device__ __align__(16) float g_fin[NN * DD];

#define SRC_EXT 0
#define SRC_CTX 1
#define SRC_ATT 2
#define DST_QKV 0
#define DST_ATT 1
#define DST_FIN 2

// ---------------- bitmap + edges ---------------------------------------------
__global__ void k_init_bitmap() {
    int w = blockIdx.x * 256 + threadIdx.x;
    int row = w >> 7, cw = w & 127;
    g_bitmap[w] = ((row >> 5) == cw) ? (1u << (row & 31)) : 0u;
}
__global__ void k_edges(const int* __restrict__ ei, int E) {
    int e = blockIdx.x * 256 + threadIdx.x;
    if (e >= E) return;
    int s = ei[e], d = ei[E + e];
    atomicOr(&g_bitmap[s * WPR + (d >> 5)], 1u << (d & 31));
    atomicOr(&g_bitmap[d * WPR + (s >> 5)], 1u << (s & 31));
}

// ---------------- mma.sync bf16 helpers --------------------------------------
__device__ __forceinline__ void mma_bf16(float* c, const uint32_t* a, const uint32_t* b) {
    asm volatile("mma.sync.aligned.m16n8k16.row.col.f32.bf16.bf16.f32 "
        "{%0,%1,%2,%3}, {%4,%5,%6,%7}, {%8,%9}, {%0,%1,%2,%3};"
        : "+f"(c[0]), "+f"(c[1]), "+f"(c[2]), "+f"(c[3])
        : "r"(a[0]), "r"(a[1]), "r"(a[2]), "r"(a[3]), "r"(b[0]), "r"(b[1]));
}
__device__ __forceinline__ uint32_t pack_bf2(float x, float y) {
    __nv_bfloat162 h = __floats2bfloat162_rn(x, y);   // .x -> low 16 bits
    return *(uint32_t*)&h;
}

// ---------------- split-bf16 tensor-core GEMM --------------------------------
// C[M x Nn] = A[M x 256] @ B[Nn x 256]^T + bias (+resid), fp32 in/out.
// Block tile BM x 128, 8 warps (2 x 4), warp tile (BM/2) x 32.
// K staged in chunks of 64 as hi/lo bf16, row pitch 72 (bank = 4r+c, conflict-free).
// D = Ah*Bh + Ah*Bl + Al*Bh, fp32 accumulate (~1e-6 rel).
#define PITCH 72   // bf16 elements per staged row
template <int BM, int SRC, int DST, bool QSCALE, bool RESID>
__global__ void __launch_bounds__(256)
k_mgemm(const float* __restrict__ Aext, const float* __restrict__ Bw,
        const float* __restrict__ bias, const float* __restrict__ resid, int Nn) {
    constexpr int MF = BM / 32;                 // m-fragments per warp
    extern __shared__ __nv_bfloat16 sm[];
    __nv_bfloat16* Ah = sm;
    __nv_bfloat16* Al = sm + BM * PITCH;
    __nv_bfloat16* Bh = sm + 2 * BM * PITCH;
    __nv_bfloat16* Bl = sm + 2 * BM * PITCH + 128 * PITCH;
    uint32_t* Ah32 = (uint32_t*)Ah; uint32_t* Al32 = (uint32_t*)Al;
    uint32_t* Bh32 = (uint32_t*)Bh; uint32_t* Bl32 = (uint32_t*)Bl;

    const float* A = (SRC == SRC_EXT) ? Aext : (SRC == SRC_CTX ? g_ctx : g_att);
    float* C = (DST == DST_QKV) ? g_qkv : (DST == DST_ATT ? g_att : g_fin);

    int t = threadIdx.x, warp = t >> 5, lane = t & 31;
    int wm = warp >> 2, wn = warp & 3;          // 2 x 4 warp grid
    int m0 = blockIdx.y * BM;
    int n0 = blockIdx.x * 128;

    const float* Arow = A + (size_t)m0 * 256;
    const float* Brow = Bw + (size_t)n0 * 256;

    float acc[MF][4][4];
#pragma unroll
    for (int i = 0; i < MF; i++)
#pragma unroll
        for (int j = 0; j < 4; j++)
#pragma unroll
            for (int k = 0; k < 4; k++) acc[i][j][k] = 0.f;

    for (int kc = 0; kc < 4; kc++) {
        // stage A chunk (BM x 64) as hi/lo bf16
        for (int p = t; p < BM * 32; p += 256) {
            int r = p >> 5, c2 = p & 31;
            float2 a2 = *(const float2*)(Arow + r * 256 + kc * 64 + c2 * 2);
            float h0 = __bfloat162float(__float2bfloat16(a2.x));
            float h1 = __bfloat162float(__float2bfloat16(a2.y));
            Ah32[r * (PITCH / 2) + c2] = pack_bf2(a2.x, a2.y);
            Al32[r * (PITCH / 2) + c2] = pack_bf2(a2.x - h0, a2.y - h1);
        }
        // stage B chunk (128 x 64)
        for (int p = t; p < 4096; p += 256) {
            int r = p >> 5, c2 = p & 31;
            float2 b2 = *(const float2*)(Brow + r * 256 + kc * 64 + c2 * 2);
            float h0 = __bfloat162float(__float2bfloat16(b2.x));
            float h1 = __bfloat162float(__float2bfloat16(b2.y));
            Bh32[r * (PITCH / 2) + c2] = pack_bf2(b2.x, b2.y);
            Bl32[r * (PITCH / 2) + c2] = pack_bf2(b2.x - h0, b2.y - h1);
        }
        __syncthreads();

#pragma unroll
        for (int ks = 0; ks < 4; ks++) {
            int kq = ks * 8 + (lane & 3);       // u32 col within chunk (lo half)
            // B fragments for this warp's 4 n-tiles
            uint32_t bh[4][2], bl[4][2];
#pragma unroll
            for (int nf = 0; nf < 4; nf++) {
                int col = wn * 32 + nf * 8 + (lane >> 2);
                bh[nf][0] = Bh32[col * (PITCH / 2) + kq];
                bh[nf][1] = Bh32[col * (PITCH / 2) + kq + 4];
                bl[nf][0] = Bl32[col * (PITCH / 2) + kq];
                bl[nf][1] = Bl32[col * (PITCH / 2) + kq + 4];
            }
#pragma unroll
            for (int mf = 0; mf < MF; mf++) {
                int row = wm * (BM / 2) + mf * 16 + (lane >> 2);
                uint32_t ah[4], al[4];
                ah[0] = Ah32[row * (PITCH / 2) + kq];
                ah[1] = Ah32[(row + 8) * (PITCH / 2) + kq];
                ah[2] = Ah32[row * (PITCH / 2) + kq + 4];
                ah[3] = Ah32[(row + 8) * (PITCH / 2) + kq + 4];
                al[0] = Al32[row * (PITCH / 2) + kq];
                al[1] = Al32[(row + 8) * (PITCH / 2) + kq];
                al[2] = Al32[row * (PITCH / 2) + kq + 4];
                al[3] = Al32[(row + 8) * (PITCH / 2) + kq + 4];
#pragma unroll
                for (int nf = 0; nf < 4; nf++) {
                    mma_bf16(acc[mf][nf], ah, bh[nf]);
                    mma_bf16(acc[mf][nf], ah, bl[nf]);
                    mma_bf16(acc[mf][nf], al, bh[nf]);
                }
            }
        }
        __syncthreads();
    }

    // epilogue: direct global stores (float2 per fragment half)
#pragma unroll
    for (int mf = 0; mf < MF; mf++) {
        int r0 = m0 + wm * (BM / 2) + mf * 16 + (lane >> 2);
#pragma unroll
        for (int nf = 0; nf < 4; nf++) {
            int c0 = n0 + wn * 32 + nf * 8 + (lane & 3) * 2;
            float b0 = bias[c0], b1 = bias[c0 + 1];
            float v0 = acc[mf][nf][0] + b0, v1 = acc[mf][nf][1] + b1;
            float v2 = acc[mf][nf][2] + b0, v3 = acc[mf][nf][3] + b1;
            if (QSCALE && c0 < 256) { v0 *= 0.125f; v1 *= 0.125f; v2 *= 0.125f; v3 *= 0.125f; }
            if (RESID) {
                const float* rp0 = resid + (size_t)r0 * 256 + c0;
                const float* rp1 = resid + (size_t)(r0 + 8) * 256 + c0;
                v0 += rp0[0]; v1 += rp0[1]; v2 += rp1[0]; v3 += rp1[1];
            }
            *(float2*)(C + (size_t)r0 * Nn + c0) = make_float2(v0, v1);
            *(float2*)(C + (size_t)(r0 + 8) * Nn + c0) = make_float2(v2, v3);
        }
    }
}

// ---------------- sparse masked multi-head attention -------------------------
__global__ void k_attn() {
    int i = blockIdx.x;
    __shared__ float q_s[256];
    __shared__ int   nbr[MAXN];
    __shared__ float sc[MAXN * 4];
    __shared__ float inv_s[4];
    __shared__ int   wsum[4];
    __shared__ int   total;
    __shared__ __align__(16) float4 vred[4][64];

    int t = threadIdx.x;
    int warp = t >> 5, lane = t & 31;
    q_s[t] = g_qkv[i * TD + t];

    // deterministic neighbor extraction: popcount + exclusive scan
    unsigned w = 0; int pc = 0;
    if (t < 128) { w = g_bitmap[i * WPR + t]; pc = __popc(w); }
    int excl = 0;
    if (t < 128) {
        int v = pc;
#pragma unroll
        for (int o = 1; o < 32; o <<= 1) {
            int u = __shfl_up_sync(0xffffffffu, v, o);
            if (lane >= o) v += u;
        }
        excl = v - pc;
        if (lane == 31) wsum[warp] = v;
    }
    __syncthreads();
    if (t == 0) {
        int s0 = wsum[0], s1 = wsum[1], s2 = wsum[2], s3 = wsum[3];
        wsum[0] = 0; wsum[1] = s0; wsum[2] = s0 + s1; wsum[3] = s0 + s1 + s2;
        total = s0 + s1 + s2 + s3;
    }
    __syncthreads();
    if (t < 128) {
        int base = wsum[warp] + excl;
        unsigned ww = w; int j = 0;
        while (ww) {
            int b = __ffs(ww) - 1;
            ww &= ww - 1;
            int p = base + j++;
            if (p < MAXN) nbr[p] = t * 32 + b;
        }
    }
    __syncthreads();
    int c = total < MAXN ? total : MAXN;

    int head = lane >> 3;
    // scores: warp per neighbor, 8 floats of K per lane
    for (int n = warp; n < c; n += 8) {
        const float* kr = g_qkv + nbr[n] * TD + 256 + lane * 8;
        float4 k0 = *(const float4*)kr;
        float4 k1 = *(const float4*)(kr + 4);
        const float* qq = q_s + lane * 8;
        float p = k0.x * qq[0] + k0.y * qq[1] + k0.z * qq[2] + k0.w * qq[3]
                + k1.x * qq[4] + k1.y * qq[5] + k1.z * qq[6] + k1.w * qq[7];
        p += __shfl_xor_sync(0xffffffffu, p, 4);
        p += __shfl_xor_sync(0xffffffffu, p, 2);
        p += __shfl_xor_sync(0xffffffffu, p, 1);
        if ((lane & 7) == 0) sc[n * 4 + head] = p;
    }
    __syncthreads();

    // softmax per head
    if (warp < 4) {
        int h = warp;
        float m = -1e30f;
        for (int n = lane; n < c; n += 32) m = fmaxf(m, sc[n * 4 + h]);
#pragma unroll
        for (int o = 16; o; o >>= 1) m = fmaxf(m, __shfl_xor_sync(0xffffffffu, m, o));
        float s = 0.f;
        for (int n = lane; n < c; n += 32) {
            float e = expf(sc[n * 4 + h] - m);
            sc[n * 4 + h] = e;
            s += e;
        }
#pragma unroll
        for (int o = 16; o; o >>= 1) s += __shfl_xor_sync(0xffffffffu, s, o);
        if (lane == 0) inv_s[h] = 1.0f / s;
    }
    __syncthreads();

    // context: float4 per thread, 4 neighbor slices, smem reduce
    int g = t >> 6;
    int q = t & 63;
    int h2 = q >> 4;
    float4 acc = make_float4(0.f, 0.f, 0.f, 0.f);
    for (int n = g; n < c; n += 4) {
        float wv = sc[n * 4 + h2];
        float4 v = *(const float4*)&g_qkv[nbr[n] * TD + 512 + q * 4];
        acc.x += wv * v.x; acc.y += wv * v.y; acc.z += wv * v.z; acc.w += wv * v.w;
    }
    vred[g][q] = acc;
    __syncthreads();
    if (t < 64) {
        float4 a = vred[0][t], b = vred[1][t], cc = vred[2][t], d = vred[3][t];
        float inv = inv_s[t >> 4];
        float4 o;
        o.x = ((a.x + b.x) + (cc.x + d.x)) * inv;
        o.y = ((a.y + b.y) + (cc.y + d.y)) * inv;
        o.z = ((a.z + b.z) + (cc.z + d.z)) * inv;
        o.w = ((a.w + b.w) + (cc.w + d.w)) * inv;
        *(float4*)&g_ctx[i * DD + t * 4] = o;
    }
}

// ---------------- LayerNorm --------------------------------------------------
__global__ void k_ln(const float* __restrict__ gamma,
                     const float* __restrict__ beta,
                     float* __restrict__ out) {
    int i = blockIdx.x, t = threadIdx.x;
    __shared__ float red[8];
    float v = g_fin[i * 256 + t];
    float s = v;
#pragma unroll
    for (int o = 16; o; o >>= 1) s += __shfl_xor_sync(0xffffffffu, s, o);
    if ((t & 31) == 0) red[t >> 5] = s;
    __syncthreads();
    float mu = 0.f;
#pragma unroll
    for (int j = 0; j < 8; j++) mu += red[j];
    mu *= (1.0f / 256.0f);
    __syncthreads();
    float d = v - mu;
    float s2 = d * d;
#pragma unroll
    for (int o = 16; o; o >>= 1) s2 += __shfl_xor_sync(0xffffffffu, s2, o);
    if ((t & 31) == 0) red[t >> 5] = s2;
    __syncthreads();
    float var = 0.f;
#pragma unroll
    for (int j = 0; j < 8; j++) var += red[j];
    var *= (1.0f / 256.0f);
    out[i * 256 + t] = d * rsqrtf(var + 1e-5f) * gamma[t] + beta[t];
}

// ---------------- launch ------------------------------------------------------
extern "C" void kernel_launch(void* const* d_in, const int* in_sizes, int n_in,
                              void* d_out, int out_size) {
    const float* nf    = (const float*)d_in[0];
    const int*   ei    = (const int*)d_in[1];
    const float* in_w  = (const float*)d_in[2];
    const float* in_b  = (const float*)d_in[3];
    const float* out_w = (const float*)d_in[4];
    const float* out_b = (const float*)d_in[5];
    const float* p_w   = (const float*)d_in[6];
    const float* p_b   = (const float*)d_in[7];
    const float* gamma = (const float*)d_in[8];
    const float* beta  = (const float*)d_in[9];
    int E = in_sizes[1] / 2;

    const int SMEM_128 = (2 * 128 + 2 * 128) * PITCH * 2;   // 73728 B
    const int SMEM_64  = (2 * 64  + 2 * 128) * PITCH * 2;   // 55296 B
    cudaFuncSetAttribute((const void*)k_mgemm<128, SRC_EXT, DST_QKV, true,  false>,
                         cudaFuncAttributeMaxDynamicSharedMemorySize, SMEM_128);
    cudaFuncSetAttribute((const void*)k_mgemm<64,  SRC_CTX, DST_ATT, false, false>,
                         cudaFuncAttributeMaxDynamicSharedMemorySize, SMEM_64);
    cudaFuncSetAttribute((const void*)k_mgemm<64,  SRC_ATT, DST_FIN, false, true>,
                         cudaFuncAttributeMaxDynamicSharedMemorySize, SMEM_64);

    k_init_bitmap<<<(NN * WPR) / 256, 256>>>();
    k_edges<<<(E + 255) / 256, 256>>>(ei, E);
    k_mgemm<128, SRC_EXT, DST_QKV, true,  false><<<dim3(TD / 128, NN / 128), 256, SMEM_128>>>(nf, in_w, in_b, nullptr, TD);
    k_attn<<<NN, 256>>>();
    k_mgemm<64,  SRC_CTX, DST_ATT, false, false><<<dim3(DD / 128, NN / 64), 256, SMEM_64>>>(nullptr, out_w, out_b, nullptr, DD);
    k_mgemm<64,  SRC_ATT, DST_FIN, false, true ><<<dim3(DD / 128, NN / 64), 256, SMEM_64>>>(nullptr, p_w, p_b, nf, DD);
    k_ln<<<NN, 256>>>(gamma, beta, (float*)d_out);
}